// round 12
// baseline (speedup 1.0000x reference)
#include <cuda_runtime.h>
#include <cuda_bf16.h>
#include <math.h>
#include <stdint.h>

// Problem constants
#define BB 4
#define TT 4096
#define HH 8
#define DD 128
#define MM (BB*TT)     // 16384
#define KDIM 1024

// ---------------- scratch (device globals: no allocs allowed) ----------------
__device__ __align__(16) float g_qkvz[(size_t)MM * 4096];
__device__ __align__(16) float g_q[(size_t)BB * HH * TT * DD];
__device__ __align__(16) float g_k[(size_t)BB * HH * TT * DD];
__device__ __align__(16) float g_v[(size_t)BB * HH * TT * DD];
__device__ __align__(16) float g_eg[(size_t)BB * HH * TT];
__device__ __align__(16) float g_be[(size_t)BB * HH * TT];
__device__ __align__(16) float g_core[(size_t)BB * TT * 1024];
// split-bf16 operands
__device__ __align__(16) __nv_bfloat16 g_xhi[(size_t)MM * KDIM];
__device__ __align__(16) __nv_bfloat16 g_xlo[(size_t)MM * KDIM];
__device__ __align__(16) __nv_bfloat16 g_wqt_hi[(size_t)4096 * KDIM];  // W_qkvz^T [N,K]
__device__ __align__(16) __nv_bfloat16 g_wqt_lo[(size_t)4096 * KDIM];
__device__ __align__(16) __nv_bfloat16 g_wot_hi[(size_t)1024 * KDIM];  // W_out^T [N,K]
__device__ __align__(16) __nv_bfloat16 g_wot_lo[(size_t)1024 * KDIM];
__device__ __align__(16) __nv_bfloat16 g_fhi[(size_t)MM * KDIM];
__device__ __align__(16) __nv_bfloat16 g_flo[(size_t)MM * KDIM];

// ============================ helpers ========================================
__device__ __forceinline__ uint32_t smem_u32(const void* p) {
    return (uint32_t)__cvta_generic_to_shared(p);
}
__device__ __forceinline__ void cp_async16(uint32_t dst, const void* src) {
    asm volatile("cp.async.cg.shared.global [%0], [%1], 16;\n" :: "r"(dst), "l"(src));
}
#define CP_COMMIT() asm volatile("cp.async.commit_group;\n" ::: "memory")
#define CP_WAIT1()  asm volatile("cp.async.wait_group 1;\n" ::: "memory")

__device__ __forceinline__ void ldm4(uint32_t* r, uint32_t addr) {
    asm volatile("ldmatrix.sync.aligned.m8n8.x4.shared.b16 {%0,%1,%2,%3}, [%4];"
                 : "=r"(r[0]), "=r"(r[1]), "=r"(r[2]), "=r"(r[3]) : "r"(addr));
}
__device__ __forceinline__ void mma16816(float* c, const uint32_t* a,
                                         const uint32_t* b) {
    asm volatile(
        "mma.sync.aligned.m16n8k16.row.col.f32.bf16.bf16.f32 "
        "{%0,%1,%2,%3}, {%4,%5,%6,%7}, {%8,%9}, {%0,%1,%2,%3};"
        : "+f"(c[0]), "+f"(c[1]), "+f"(c[2]), "+f"(c[3])
        : "r"(a[0]), "r"(a[1]), "r"(a[2]), "r"(a[3]), "r"(b[0]), "r"(b[1]));
}

// ============ HMMA split-bf16 GEMM: C[M,N] = A[M,K] @ Bt[N,K]^T ==============
// BM=BN=128, BK=32, 256 threads (2x4 warps, 64x32 warp tiles).
// XOR-swizzled 64B rows (chunk c ^ ((row>>1)&3)) -> compact, LDSM-phase
// conflict-free. 3-stage cp.async pipeline, 2 CTAs/SM, 1 barrier/iter.
#define MATB  8192               // 128 rows * 64 B
#define STGB  (4 * MATB)         // 32768: Ahi,Alo,Bhi,Blo
#define NSTG  3
#define GEMM_SMEM (NSTG * STGB)  // 98304

__global__ __launch_bounds__(256, 2) void hmma_gemm(
    const __nv_bfloat16* __restrict__ Ahi, const __nv_bfloat16* __restrict__ Alo,
    const __nv_bfloat16* __restrict__ Bhi, const __nv_bfloat16* __restrict__ Blo,
    float* __restrict__ C, int ldc) {
    extern __shared__ __align__(128) char smem[];
    const int tid = threadIdx.x;
    const int wid = tid >> 5, lane = tid & 31;
    const int wm = wid >> 2, wn = wid & 3;          // warp grid 2 x 4
    const int n0 = blockIdx.x << 7;
    const int m0 = blockIdx.y << 7;
    const uint32_t sb = smem_u32(smem);

    // ---- loader geometry: row = tid>>1, two 16B chunks (logical c0, c0+1) ---
    const int row_ld = tid >> 1;
    const int c0 = (tid & 1) * 2;
    const uint32_t selL = ((uint32_t)row_ld >> 1) & 3;
    const uint32_t soR = (uint32_t)row_ld * 64;
    const uint32_t sc0 = soR + (((uint32_t)c0 ^ selL) * 16);
    const uint32_t sc1 = soR + ((((uint32_t)c0 + 1) ^ selL) * 16);
    const __nv_bfloat16* pAhi = Ahi + (size_t)(m0 + row_ld) * KDIM;
    const __nv_bfloat16* pAlo = Alo + (size_t)(m0 + row_ld) * KDIM;
    const __nv_bfloat16* pBhi = Bhi + (size_t)(n0 + row_ld) * KDIM;
    const __nv_bfloat16* pBlo = Blo + (size_t)(n0 + row_ld) * KDIM;

#define LOADST(s, kb) do { \
        uint32_t b_ = sb + (uint32_t)(s) * STGB; \
        size_t g0_ = (size_t)(kb) * 32 + c0 * 8; \
        cp_async16(b_ + 0 * MATB + sc0, pAhi + g0_); \
        cp_async16(b_ + 0 * MATB + sc1, pAhi + g0_ + 8); \
        cp_async16(b_ + 1 * MATB + sc0, pAlo + g0_); \
        cp_async16(b_ + 1 * MATB + sc1, pAlo + g0_ + 8); \
        cp_async16(b_ + 2 * MATB + sc0, pBhi + g0_); \
        cp_async16(b_ + 2 * MATB + sc1, pBhi + g0_ + 8); \
        cp_async16(b_ + 3 * MATB + sc0, pBlo + g0_); \
        cp_async16(b_ + 3 * MATB + sc1, pBlo + g0_ + 8); \
    } while (0)

    // ---- ldmatrix per-lane swizzled offsets ----
    const uint32_t aBase = (uint32_t)(wm * 64 + (lane & 15)) * 64;
    const uint32_t selA = (((uint32_t)(lane & 15)) >> 1) & 3;
    const uint32_t abit = (uint32_t)(lane >> 4);
    const uint32_t aC0 = ((0 + abit) ^ selA) * 16;   // k16=0
    const uint32_t aC1 = ((2 + abit) ^ selA) * 16;   // k16=1
    const uint32_t bRow = ((uint32_t)(lane >> 4) << 3) + (uint32_t)(lane & 7);
    const uint32_t bBase = (uint32_t)(wn * 32 + (int)bRow) * 64;
    const uint32_t selB = (bRow >> 1) & 3;
    const uint32_t bbit = ((uint32_t)lane >> 3) & 1;
    const uint32_t bC0 = ((0 + bbit) ^ selB) * 16;
    const uint32_t bC1 = ((2 + bbit) ^ selB) * 16;

    float acc[4][4][4];
#pragma unroll
    for (int i = 0; i < 4; i++)
#pragma unroll
        for (int j = 0; j < 4; j++)
#pragma unroll
            for (int r = 0; r < 4; r++) acc[i][j][r] = 0.f;

    const int ITERS = KDIM / 32;   // 32
    LOADST(0, 0); CP_COMMIT();
    LOADST(1, 1); CP_COMMIT();

    int stage = 0;
    for (int it = 0; it < ITERS; it++) {
        CP_WAIT1();
        __syncthreads();
        if (it + 2 < ITERS) {
            int ns = stage + 2; if (ns >= 3) ns -= 3;
            LOADST(ns, it + 2);
        }
        CP_COMMIT();

        const uint32_t base = sb + (uint32_t)stage * STGB;
#pragma unroll
        for (int k16 = 0; k16 < 2; k16++) {
            const uint32_t aC = k16 ? aC1 : aC0;
            const uint32_t bC = k16 ? bC1 : bC0;
            uint32_t ah[4][4], bh[2][4], bl[2][4];
#pragma unroll
            for (int mf = 0; mf < 4; mf++)
                ldm4(ah[mf], base + 0 * MATB + aBase + mf * 1024 + aC);
#pragma unroll
            for (int p = 0; p < 2; p++) {
                ldm4(bh[p], base + 2 * MATB + bBase + p * 1024 + bC);
                ldm4(bl[p], base + 3 * MATB + bBase + p * 1024 + bC);
            }
#pragma unroll
            for (int mf = 0; mf < 4; mf++)
#pragma unroll
                for (int nf = 0; nf < 4; nf++)
                    mma16816(acc[mf][nf], ah[mf], &bh[nf >> 1][(nf & 1) * 2]);
#pragma unroll
            for (int mf = 0; mf < 4; mf++)
#pragma unroll
                for (int nf = 0; nf < 4; nf++)
                    mma16816(acc[mf][nf], ah[mf], &bl[nf >> 1][(nf & 1) * 2]);
            uint32_t al[4][4];
#pragma unroll
            for (int mf = 0; mf < 4; mf++)
                ldm4(al[mf], base + 1 * MATB + aBase + mf * 1024 + aC);
#pragma unroll
            for (int mf = 0; mf < 4; mf++)
#pragma unroll
                for (int nf = 0; nf < 4; nf++)
                    mma16816(acc[mf][nf], al[mf], &bh[nf >> 1][(nf & 1) * 2]);
        }
        if (++stage == 3) stage = 0;
    }

    // ---- epilogue ----
#pragma unroll
    for (int mf = 0; mf < 4; mf++) {
        const int r0 = m0 + wm * 64 + mf * 16 + (lane >> 2);
#pragma unroll
        for (int nf = 0; nf < 4; nf++) {
            const int c0e = n0 + wn * 32 + nf * 8 + (lane & 3) * 2;
            float2 v01 = make_float2(acc[mf][nf][0], acc[mf][nf][1]);
            float2 v23 = make_float2(acc[mf][nf][2], acc[mf][nf][3]);
            *(float2*)(C + (size_t)r0 * ldc + c0e) = v01;
            *(float2*)(C + (size_t)(r0 + 8) * ldc + c0e) = v23;
        }
    }
#undef LOADST
}

// ---------------- fp32 -> bf16 hi/lo split (elementwise) ---------------------
__global__ __launch_bounds__(256) void split_f32(
    const float* __restrict__ src, __nv_bfloat16* __restrict__ hi,
    __nv_bfloat16* __restrict__ lo, int n) {
    int i = blockIdx.x * 256 + threadIdx.x;
    if (i < n) {
        float v = src[i];
        __nv_bfloat16 h = __float2bfloat16(v);
        hi[i] = h;
        lo[i] = __float2bfloat16(v - __bfloat162float(h));
    }
}

// ---------------- W[K,N] -> Wt_hi/lo[N,K] transpose + split ------------------
__global__ __launch_bounds__(256) void tsplit(
    const float* __restrict__ W, __nv_bfloat16* __restrict__ hi,
    __nv_bfloat16* __restrict__ lo, int K, int N) {
    __shared__ float t[32][33];
    const int n0 = blockIdx.x * 32, k0 = blockIdx.y * 32;
    const int tx = threadIdx.x & 31, ty = threadIdx.x >> 5;   // 32 x 8
#pragma unroll
    for (int j = 0; j < 4; j++)
        t[ty + 8 * j][tx] = W[(size_t)(k0 + ty + 8 * j) * N + n0 + tx];
    __syncthreads();
#pragma unroll
    for (int j = 0; j < 4; j++) {
        float v = t[tx][ty + 8 * j];
        __nv_bfloat16 h = __float2bfloat16(v);
        size_t o = (size_t)(n0 + ty + 8 * j) * K + k0 + tx;
        hi[o] = h;
        lo[o] = __float2bfloat16(v - __bfloat162float(h));
    }
}

// ---------------- ba projection: 4 rows per warp -----------------------------
__global__ __launch_bounds__(256) void ba_kernel(
    const float* __restrict__ x, const float* __restrict__ Wba,
    const float* __restrict__ dt_bias, const float* __restrict__ A_log) {
    const int gw4 = (int)((blockIdx.x * 256 + threadIdx.x) >> 5);  // warp idx
    const int lane = threadIdx.x & 31;
    const int row0 = gw4 * 4;
    if (row0 >= MM) return;
    const float* xr0 = x + (size_t)row0 * 1024;

    float acc[4][16];
#pragma unroll
    for (int r = 0; r < 4; r++)
#pragma unroll
        for (int j = 0; j < 16; j++) acc[r][j] = 0.f;

    for (int i = lane; i < 1024; i += 32) {
        const float4* wr = (const float4*)(Wba + (size_t)i * 16);
        float4 w0 = wr[0], w1 = wr[1], w2 = wr[2], w3 = wr[3];
        float xv[4] = {xr0[i], xr0[1024 + i], xr0[2048 + i], xr0[3072 + i]};
#pragma unroll
        for (int r = 0; r < 4; r++) {
            acc[r][0] = fmaf(xv[r], w0.x, acc[r][0]);
            acc[r][1] = fmaf(xv[r], w0.y, acc[r][1]);
            acc[r][2] = fmaf(xv[r], w0.z, acc[r][2]);
            acc[r][3] = fmaf(xv[r], w0.w, acc[r][3]);
            acc[r][4] = fmaf(xv[r], w1.x, acc[r][4]);
            acc[r][5] = fmaf(xv[r], w1.y, acc[r][5]);
            acc[r][6] = fmaf(xv[r], w1.z, acc[r][6]);
            acc[r][7] = fmaf(xv[r], w1.w, acc[r][7]);
            acc[r][8] = fmaf(xv[r], w2.x, acc[r][8]);
            acc[r][9] = fmaf(xv[r], w2.y, acc[r][9]);
            acc[r][10] = fmaf(xv[r], w2.z, acc[r][10]);
            acc[r][11] = fmaf(xv[r], w2.w, acc[r][11]);
            acc[r][12] = fmaf(xv[r], w3.x, acc[r][12]);
            acc[r][13] = fmaf(xv[r], w3.y, acc[r][13]);
            acc[r][14] = fmaf(xv[r], w3.z, acc[r][14]);
            acc[r][15] = fmaf(xv[r], w3.w, acc[r][15]);
        }
    }
#pragma unroll
    for (int r = 0; r < 4; r++) {
#pragma unroll
        for (int j = 0; j < 16; j++) {
#pragma unroll
            for (int s = 16; s; s >>= 1)
                acc[r][j] += __shfl_xor_sync(0xffffffffu, acc[r][j], s);
        }
        if (lane < 8) {
            const int h = lane;
            const int gw = row0 + r;
            float bet = 1.0f / (1.0f + expf(-acc[r][h]));
            float al = acc[r][8 + h] + dt_bias[h];
            float sp = (al > 20.0f) ? al : log1pf(expf(al));
            float g = -expf(A_log[h]) * sp;
            const int b = gw >> 12, t = gw & (TT - 1);
            size_t o = ((size_t)(b * HH + h)) * TT + t;
            g_be[o] = bet;
            g_eg[o] = expf(g);
        }
    }
}

// ------- depthwise causal conv (K=4) + SiLU, 4 t per thread, scatter --------
__global__ __launch_bounds__(256) void conv_kernel(
    const float* __restrict__ cw, const float* __restrict__ cb) {
    const size_t idx = (size_t)blockIdx.x * 256 + threadIdx.x;
    const size_t total = (size_t)BB * (TT / 4) * 3072;
    if (idx >= total) return;
    const int c = (int)(idx % 3072);
    const size_t bt4 = idx / 3072;
    const int b = (int)(bt4 >> 10);            // TT/4 = 1024 per batch
    const int t0 = ((int)(bt4 & 1023)) << 2;

    const float* row = g_qkvz + ((size_t)b * TT + t0) * 4096 + c;
    float xv[7];
#pragma unroll
    for (int j = 0; j < 7; j++) {
        int tt = t0 - 3 + j;
        xv[j] = (tt >= 0) ? row[(size_t)(j - 3) * 4096] : 0.f;
    }
    const float* w = cw + (size_t)c * 4;
    const float w0 = w[0], w1 = w[1], w2 = w[2], w3 = w[3];
    const float bias = cb[c];

    const int h = (c >> 7) & 7;
    const int d = c & 127;
    const int sec = c >> 10;                   // 0=q 1=k 2=v
    float* outp;
    float scale;
    if (sec == 0)      { outp = g_q; scale = 0.08838834764831845f; }
    else if (sec == 1) { outp = g_k; scale = 1.f; }
    else               { outp = g_v; scale = 1.f; }
    const size_t obase = (((size_t)(b * HH + h)) * TT + t0) * DD + d;

#pragma unroll
    for (int i = 0; i < 4; i++) {
        float y = bias;
        y = fmaf(xv[i], w0, y);
        y = fmaf(xv[i + 1], w1, y);
        y = fmaf(xv[i + 2], w2, y);
        y = fmaf(xv[i + 3], w3, y);
        float o = y / (1.0f + expf(-y)) * scale;
        outp[obase + (size_t)i * DD] = o;
    }
}

// ---------------- gated delta rule: smem-staged sequential scan --------------
// 128 blocks (32 bh x 4 v-splits), 512 threads (16 warps = 4/SMSP for latency
// hiding). Thread owns 8 rows x 1 col of S; 16-lane shfl reductions.
// 16-step chunks staged through smem via cp.async double buffer.
#define SC_CHUNK 16
#define SC_NCHUNK (TT / SC_CHUNK)      // 256
#define SC_GSTRIDE 1040                // bytes between 16-row groups (8 groups)
#define SC_KBYTES (8 * SC_GSTRIDE)     // 8320
#define SC_VOFF  (2 * SC_KBYTES)       // 16640
#define SC_EGOFF (SC_VOFF + 2048)      // 18688
#define SC_BEOFF (SC_EGOFF + 64)       // 18752
#define SC_BUFB  18816

__global__ __launch_bounds__(512, 1) void scan_kernel() {
    __shared__ __align__(16) char sscan[2][SC_BUFB];

    const int bh = blockIdx.x >> 2;
    const int split = blockIdx.x & 3;
    const int tid = threadIdx.x;
    const int colloc = tid >> 4;            // 0..31 (local col)
    const int g4 = tid & 15;                // 8-row group: rows g4*8..g4*8+7
    const int b = bh >> 3, h = bh & 7;

    const float* kbase = g_k + (size_t)bh * TT * DD;
    const float* qbase = g_q + (size_t)bh * TT * DD;
    const float* vbase = g_v + (size_t)bh * TT * DD + split * 32;
    const float* egbase = g_eg + (size_t)bh * TT;
    const float* bebase = g_be + (size_t)bh * TT;
    float* ob = g_core + (size_t)b * TT * 1024 + (size_t)h * DD
              + (split << 5) + colloc;

    // loader roles (per chunk): k/q 1 chunk each (512 chunks per matrix)
    const int kt = tid >> 5, kj = tid & 31;
    const uint32_t kd = (uint32_t)((kj >> 2) * SC_GSTRIDE + kt * 64 + (kj & 3) * 16);
    const uint32_t sb0 = smem_u32(&sscan[0][0]);
    const uint32_t sb1 = smem_u32(&sscan[1][0]);

#define SC_LOAD(cc, buf) do { \
        const uint32_t bp = (buf) ? sb1 : sb0; \
        size_t t0_ = (size_t)(cc) * SC_CHUNK; \
        cp_async16(bp + kd, kbase + (t0_ + kt) * 128 + kj * 4); \
        cp_async16(bp + SC_KBYTES + kd, qbase + (t0_ + kt) * 128 + kj * 4); \
        if (tid < 128) { \
            int vt_ = tid >> 3, vj_ = tid & 7; \
            cp_async16(bp + SC_VOFF + vt_ * 128 + vj_ * 16, \
                       vbase + (t0_ + vt_) * 128 + vj_ * 4); \
        } else if (tid < 132) { \
            cp_async16(bp + SC_EGOFF + (tid - 128) * 16, egbase + t0_ + (tid - 128) * 4); \
        } else if (tid < 136) { \
            cp_async16(bp + SC_BEOFF + (tid - 132) * 16, bebase + t0_ + (tid - 132) * 4); \
        } \
        CP_COMMIT(); \
    } while (0)

    float S[8];
#pragma unroll
    for (int i = 0; i < 8; i++) S[i] = 0.f;
    float oprev = 0.f;
    const bool leader = (tid & 15) == 0;
    // this thread's 8 rows: group g4>>1 (16 rows), half (g4&1)*8
    const uint32_t krd = (uint32_t)((g4 >> 1) * SC_GSTRIDE + (g4 & 1) * 32);

    SC_LOAD(0, 0);
    SC_LOAD(1, 1);

    for (int c = 0; c < SC_NCHUNK; c++) {
        CP_WAIT1();                  // chunk c landed (own loads)
        __syncthreads();             // all threads' chunk-c loads visible

        const char* bufp = &sscan[c & 1][0];
        const char* kgp = bufp + krd;
        const char* qgp = bufp + SC_KBYTES + krd;
        const float* vsp = (const float*)(bufp + SC_VOFF) + colloc;
        const float* egp = (const float*)(bufp + SC_EGOFF);
        const float* bep = (const float*)(bufp + SC_BEOFF);

#pragma unroll 4
        for (int tt = 0; tt < SC_CHUNK; tt++) {
            float4 k0 = *(const float4*)(kgp + tt * 64);
            float4 k1 = *(const float4*)(kgp + tt * 64 + 16);
            float4 q0 = *(const float4*)(qgp + tt * 64);
            float4 q1 = *(const float4*)(qgp + tt * 64 + 16);
            const float vt = vsp[tt * 32];
            const float egt = egp[tt];
            const float bet = bep[tt];
            float kr[8], qr[8];
#pragma unroll
            for (int i = 0; i < 4; i++) {
                kr[i] = ((const float*)&k0)[i]; kr[4 + i] = ((const float*)&k1)[i];
                qr[i] = ((const float*)&q0)[i]; qr[4 + i] = ((const float*)&q1)[i];
            }

            // deferred reduce of previous step's output (independent chain)
            float ord = oprev;
            ord += __shfl_xor_sync(0xffffffffu, ord, 1);

            // s = k . S_old over this thread's 8 rows
            float s0 = 0.f, s1 = 0.f;
#pragma unroll
            for (int i = 0; i < 4; i++) {
                s0 = fmaf(kr[i],     S[i],     s0);
                s1 = fmaf(kr[4 + i], S[4 + i], s1);
            }
            ord += __shfl_xor_sync(0xffffffffu, ord, 2);
            float s = s0 + s1;
            ord += __shfl_xor_sync(0xffffffffu, ord, 4);
            s += __shfl_xor_sync(0xffffffffu, s, 1);
            ord += __shfl_xor_sync(0xffffffffu, ord, 8);
            s += __shfl_xor_sync(0xffffffffu, s, 2);
            const int t = c * SC_CHUNK + tt;
            if (leader && t) ob[(size_t)(t - 1) * 1024] = ord;
            s += __shfl_xor_sync(0xffffffffu, s, 4);
            s += __shfl_xor_sync(0xffffffffu, s, 8);
            const float delta = (vt - egt * s) * bet;

            // S = eg*S + k*delta ; o partial = q . S_new
            float o0 = 0.f, o1 = 0.f;
#pragma unroll
            for (int i = 0; i < 4; i++) {
                S[i]     = fmaf(kr[i],     delta, egt * S[i]);
                o0 = fmaf(qr[i], S[i], o0);
                S[4 + i] = fmaf(kr[4 + i], delta, egt * S[4 + i]);
                o1 = fmaf(qr[4 + i], S[4 + i], o1);
            }
            oprev = o0 + o1;
        }

        __syncthreads();             // all threads done reading buf (c&1)
        if (c + 2 < SC_NCHUNK) SC_LOAD(c + 2, c & 1);
        else CP_COMMIT();            // keep group accounting exact
    }

    // final deferred store (t = TT-1)
    float ord = oprev;
    ord += __shfl_xor_sync(0xffffffffu, ord, 1);
    ord += __shfl_xor_sync(0xffffffffu, ord, 2);
    ord += __shfl_xor_sync(0xffffffffu, ord, 4);
    ord += __shfl_xor_sync(0xffffffffu, ord, 8);
    if (leader) ob[(size_t)(TT - 1) * 1024] = ord;
#undef SC_LOAD
}

// ---------------- fused RMSNorm * w * silu(z) -> bf16 hi/lo ------------------
__global__ __launch_bounds__(256) void gate_kernel(const float* __restrict__ nw) {
    const int bt = blockIdx.x;
    const int tid = threadIdx.x;
    const float* cr = g_core + (size_t)bt * 1024;
    const float* zr = g_qkvz + (size_t)bt * 4096 + 3072;

    float cs[4];
    float ss = 0.f;
#pragma unroll
    for (int u = 0; u < 4; u++) {
        cs[u] = cr[tid + u * 256];
        ss = fmaf(cs[u], cs[u], ss);
    }
#pragma unroll
    for (int s = 16; s; s >>= 1) ss += __shfl_xor_sync(0xffffffffu, ss, s);
    __shared__ float ws[8];
    if ((tid & 31) == 0) ws[tid >> 5] = ss;
    __syncthreads();
    float tot = ws[0] + ws[1] + ws[2] + ws[3] + ws[4] + ws[5] + ws[6] + ws[7];
    const float rms = rsqrtf(tot * (1.0f / 1024.0f) + 1e-6f);

#pragma unroll
    for (int u = 0; u < 4; u++) {
        const int i = tid + u * 256;
        float z = zr[i];
        float sz = z / (1.0f + expf(-z));
        float fv = cs[u] * rms * nw[i] * sz;
        __nv_bfloat16 hbits = __float2bfloat16(fv);
        size_t o = (size_t)bt * 1024 + i;
        g_fhi[o] = hbits;
        g_flo[o] = __float2bfloat16(fv - __bfloat162float(hbits));
    }
}

// ---------------- launch ------------------------------------------------------
extern "C" void kernel_launch(void* const* d_in, const int* in_sizes, int n_in,
                              void* d_out, int out_size) {
    const float* x       = (const float*)d_in[0];
    const float* W_qkvz  = (const float*)d_in[1];
    const float* W_ba    = (const float*)d_in[2];
    const float* conv_w  = (const float*)d_in[3];
    const float* conv_b  = (const float*)d_in[4];
    const float* dt_bias = (const float*)d_in[5];
    const float* A_log   = (const float*)d_in[6];
    const float* norm_w  = (const float*)d_in[7];
    const float* W_out   = (const float*)d_in[8];
    float* out = (float*)d_out;

    // idempotent; not stream-ordered, capture-safe
    (void)cudaFuncSetAttribute(hmma_gemm,
        cudaFuncAttributeMaxDynamicSharedMemorySize, GEMM_SMEM);

    float* qkvz_ptr;  cudaGetSymbolAddress((void**)&qkvz_ptr, g_qkvz);
    __nv_bfloat16 *xhi, *xlo, *wqh, *wql, *woh, *wol, *fhi, *flo;
    cudaGetSymbolAddress((void**)&xhi, g_xhi);
    cudaGetSymbolAddress((void**)&xlo, g_xlo);
    cudaGetSymbolAddress((void**)&wqh, g_wqt_hi);
    cudaGetSymbolAddress((void**)&wql, g_wqt_lo);
    cudaGetSymbolAddress((void**)&woh, g_wot_hi);
    cudaGetSymbolAddress((void**)&wol, g_wot_lo);
    cudaGetSymbolAddress((void**)&fhi, g_fhi);
    cudaGetSymbolAddress((void**)&flo, g_flo);

    const int M = MM;  // 16384

    // 0) operand prep: split x; transpose+split weights
    split_f32<<<(M * KDIM) / 256, 256>>>(x, xhi, xlo, M * KDIM);
    tsplit<<<dim3(4096 / 32, KDIM / 32), 256>>>(W_qkvz, wqh, wql, KDIM, 4096);
    tsplit<<<dim3(1024 / 32, KDIM / 32), 256>>>(W_out, woh, wol, KDIM, 1024);

    // 1) qkvz = x @ W_qkvz  (HMMA split-bf16)
    hmma_gemm<<<dim3(4096 / 128, M / 128), 256, GEMM_SMEM>>>(
        xhi, xlo, wqh, wql, qkvz_ptr, 4096);

    // 2) ba projection + beta / exp(g)
    ba_kernel<<<(M / 4) * 32 / 256, 256>>>(x, W_ba, dt_bias, A_log);
    // 3) causal depthwise conv + SiLU -> q,k,v
    conv_kernel<<<(unsigned)(((size_t)BB * (TT / 4) * 3072 + 255) / 256), 256>>>(
        conv_w, conv_b);
    // 4) gated delta rule scan (smem-staged, 512 threads)
    scan_kernel<<<128, 512>>>();
    // 5) RMSNorm-gate -> fused hi/lo
    gate_kernel<<<M, 256>>>(norm_w);
    // 6) out = fused @ W_out  (HMMA split-bf16)
    hmma_gemm<<<dim3(1024 / 128, M / 128), 256, GEMM_SMEM>>>(
        fhi, flo, woh, wol, out, 1024);
}

// round 14
// speedup vs baseline: 1.2496x; 1.2496x over previous
#include <cuda_runtime.h>
#include <cuda_bf16.h>
#include <math.h>
#include <stdint.h>

// Problem constants
#define BB 4
#define TT 4096
#define HH 8
#define DD 128
#define MM (BB*TT)     // 16384
#define KDIM 1024

// ---------------- scratch (device globals: no allocs allowed) ----------------
__device__ __align__(16) float g_qkvz[(size_t)MM * 4096];
__device__ __align__(16) float g_q[(size_t)BB * HH * TT * DD];
__device__ __align__(16) float g_k[(size_t)BB * HH * TT * DD];
__device__ __align__(16) float g_v[(size_t)BB * HH * TT * DD];
__device__ __align__(16) float g_eg[(size_t)BB * HH * TT];
__device__ __align__(16) float g_be[(size_t)BB * HH * TT];
__device__ __align__(16) float g_core[(size_t)BB * TT * 1024];
// split-bf16 operands
__device__ __align__(16) __nv_bfloat16 g_xhi[(size_t)MM * KDIM];
__device__ __align__(16) __nv_bfloat16 g_xlo[(size_t)MM * KDIM];
__device__ __align__(16) __nv_bfloat16 g_wqt_hi[(size_t)4096 * KDIM];  // W_qkvz^T [N,K]
__device__ __align__(16) __nv_bfloat16 g_wqt_lo[(size_t)4096 * KDIM];
__device__ __align__(16) __nv_bfloat16 g_wot_hi[(size_t)1024 * KDIM];  // W_out^T [N,K]
__device__ __align__(16) __nv_bfloat16 g_wot_lo[(size_t)1024 * KDIM];
__device__ __align__(16) __nv_bfloat16 g_fhi[(size_t)MM * KDIM];
__device__ __align__(16) __nv_bfloat16 g_flo[(size_t)MM * KDIM];

// ============================ helpers ========================================
__device__ __forceinline__ uint32_t smem_u32(const void* p) {
    return (uint32_t)__cvta_generic_to_shared(p);
}
__device__ __forceinline__ void cp_async16(uint32_t dst, const void* src) {
    asm volatile("cp.async.cg.shared.global [%0], [%1], 16;\n" :: "r"(dst), "l"(src));
}
#define CP_COMMIT() asm volatile("cp.async.commit_group;\n" ::: "memory")
#define CP_WAIT1()  asm volatile("cp.async.wait_group 1;\n" ::: "memory")

__device__ __forceinline__ void ldm4(uint32_t* r, uint32_t addr) {
    asm volatile("ldmatrix.sync.aligned.m8n8.x4.shared.b16 {%0,%1,%2,%3}, [%4];"
                 : "=r"(r[0]), "=r"(r[1]), "=r"(r[2]), "=r"(r[3]) : "r"(addr));
}
__device__ __forceinline__ void mma16816(float* c, const uint32_t* a,
                                         const uint32_t* b) {
    asm volatile(
        "mma.sync.aligned.m16n8k16.row.col.f32.bf16.bf16.f32 "
        "{%0,%1,%2,%3}, {%4,%5,%6,%7}, {%8,%9}, {%0,%1,%2,%3};"
        : "+f"(c[0]), "+f"(c[1]), "+f"(c[2]), "+f"(c[3])
        : "r"(a[0]), "r"(a[1]), "r"(a[2]), "r"(a[3]), "r"(b[0]), "r"(b[1]));
}

// ============ HMMA split-bf16 GEMM: C[M,N] = A[M,K] @ Bt[N,K]^T ==============
// BM=BN=128, BK=32, 256 threads (2x4 warps, 64x32 warp tiles).
// XOR-swizzled 64B rows, 3-stage cp.async pipeline, 2 CTAs/SM.
#define MATB  8192               // 128 rows * 64 B
#define STGB  (4 * MATB)         // 32768: Ahi,Alo,Bhi,Blo
#define NSTG  3
#define GEMM_SMEM (NSTG * STGB)  // 98304

__global__ __launch_bounds__(256, 2) void hmma_gemm(
    const __nv_bfloat16* __restrict__ Ahi, const __nv_bfloat16* __restrict__ Alo,
    const __nv_bfloat16* __restrict__ Bhi, const __nv_bfloat16* __restrict__ Blo,
    float* __restrict__ C, int ldc) {
    extern __shared__ __align__(128) char smem[];
    const int tid = threadIdx.x;
    const int wid = tid >> 5, lane = tid & 31;
    const int wm = wid >> 2, wn = wid & 3;          // warp grid 2 x 4
    const int n0 = blockIdx.x << 7;
    const int m0 = blockIdx.y << 7;
    const uint32_t sb = smem_u32(smem);

    const int row_ld = tid >> 1;
    const int c0 = (tid & 1) * 2;
    const uint32_t selL = ((uint32_t)row_ld >> 1) & 3;
    const uint32_t soR = (uint32_t)row_ld * 64;
    const uint32_t sc0 = soR + (((uint32_t)c0 ^ selL) * 16);
    const uint32_t sc1 = soR + ((((uint32_t)c0 + 1) ^ selL) * 16);
    const __nv_bfloat16* pAhi = Ahi + (size_t)(m0 + row_ld) * KDIM;
    const __nv_bfloat16* pAlo = Alo + (size_t)(m0 + row_ld) * KDIM;
    const __nv_bfloat16* pBhi = Bhi + (size_t)(n0 + row_ld) * KDIM;
    const __nv_bfloat16* pBlo = Blo + (size_t)(n0 + row_ld) * KDIM;

#define LOADST(s, kb) do { \
        uint32_t b_ = sb + (uint32_t)(s) * STGB; \
        size_t g0_ = (size_t)(kb) * 32 + c0 * 8; \
        cp_async16(b_ + 0 * MATB + sc0, pAhi + g0_); \
        cp_async16(b_ + 0 * MATB + sc1, pAhi + g0_ + 8); \
        cp_async16(b_ + 1 * MATB + sc0, pAlo + g0_); \
        cp_async16(b_ + 1 * MATB + sc1, pAlo + g0_ + 8); \
        cp_async16(b_ + 2 * MATB + sc0, pBhi + g0_); \
        cp_async16(b_ + 2 * MATB + sc1, pBhi + g0_ + 8); \
        cp_async16(b_ + 3 * MATB + sc0, pBlo + g0_); \
        cp_async16(b_ + 3 * MATB + sc1, pBlo + g0_ + 8); \
    } while (0)

    const uint32_t aBase = (uint32_t)(wm * 64 + (lane & 15)) * 64;
    const uint32_t selA = (((uint32_t)(lane & 15)) >> 1) & 3;
    const uint32_t abit = (uint32_t)(lane >> 4);
    const uint32_t aC0 = ((0 + abit) ^ selA) * 16;   // k16=0
    const uint32_t aC1 = ((2 + abit) ^ selA) * 16;   // k16=1
    const uint32_t bRow = ((uint32_t)(lane >> 4) << 3) + (uint32_t)(lane & 7);
    const uint32_t bBase = (uint32_t)(wn * 32 + (int)bRow) * 64;
    const uint32_t selB = (bRow >> 1) & 3;
    const uint32_t bbit = ((uint32_t)lane >> 3) & 1;
    const uint32_t bC0 = ((0 + bbit) ^ selB) * 16;
    const uint32_t bC1 = ((2 + bbit) ^ selB) * 16;

    float acc[4][4][4];
#pragma unroll
    for (int i = 0; i < 4; i++)
#pragma unroll
        for (int j = 0; j < 4; j++)
#pragma unroll
            for (int r = 0; r < 4; r++) acc[i][j][r] = 0.f;

    const int ITERS = KDIM / 32;   // 32
    LOADST(0, 0); CP_COMMIT();
    LOADST(1, 1); CP_COMMIT();

    int stage = 0;
    for (int it = 0; it < ITERS; it++) {
        CP_WAIT1();
        __syncthreads();
        if (it + 2 < ITERS) {
            int ns = stage + 2; if (ns >= 3) ns -= 3;
            LOADST(ns, it + 2);
        }
        CP_COMMIT();

        const uint32_t base = sb + (uint32_t)stage * STGB;
#pragma unroll
        for (int k16 = 0; k16 < 2; k16++) {
            const uint32_t aC = k16 ? aC1 : aC0;
            const uint32_t bC = k16 ? bC1 : bC0;
            uint32_t ah[4][4], bh[2][4], bl[2][4];
#pragma unroll
            for (int mf = 0; mf < 4; mf++)
                ldm4(ah[mf], base + 0 * MATB + aBase + mf * 1024 + aC);
#pragma unroll
            for (int p = 0; p < 2; p++) {
                ldm4(bh[p], base + 2 * MATB + bBase + p * 1024 + bC);
                ldm4(bl[p], base + 3 * MATB + bBase + p * 1024 + bC);
            }
#pragma unroll
            for (int mf = 0; mf < 4; mf++)
#pragma unroll
                for (int nf = 0; nf < 4; nf++)
                    mma16816(acc[mf][nf], ah[mf], &bh[nf >> 1][(nf & 1) * 2]);
#pragma unroll
            for (int mf = 0; mf < 4; mf++)
#pragma unroll
                for (int nf = 0; nf < 4; nf++)
                    mma16816(acc[mf][nf], ah[mf], &bl[nf >> 1][(nf & 1) * 2]);
            uint32_t al[4][4];
#pragma unroll
            for (int mf = 0; mf < 4; mf++)
                ldm4(al[mf], base + 1 * MATB + aBase + mf * 1024 + aC);
#pragma unroll
            for (int mf = 0; mf < 4; mf++)
#pragma unroll
                for (int nf = 0; nf < 4; nf++)
                    mma16816(acc[mf][nf], al[mf], &bh[nf >> 1][(nf & 1) * 2]);
        }
        if (++stage == 3) stage = 0;
    }

    // ---- epilogue ----
#pragma unroll
    for (int mf = 0; mf < 4; mf++) {
        const int r0 = m0 + wm * 64 + mf * 16 + (lane >> 2);
#pragma unroll
        for (int nf = 0; nf < 4; nf++) {
            const int c0e = n0 + wn * 32 + nf * 8 + (lane & 3) * 2;
            float2 v01 = make_float2(acc[mf][nf][0], acc[mf][nf][1]);
            float2 v23 = make_float2(acc[mf][nf][2], acc[mf][nf][3]);
            *(float2*)(C + (size_t)r0 * ldc + c0e) = v01;
            *(float2*)(C + (size_t)(r0 + 8) * ldc + c0e) = v23;
        }
    }
#undef LOADST
}

// ---------------- fp32 -> bf16 hi/lo split (elementwise) ---------------------
__global__ __launch_bounds__(256) void split_f32(
    const float* __restrict__ src, __nv_bfloat16* __restrict__ hi,
    __nv_bfloat16* __restrict__ lo, int n) {
    int i = blockIdx.x * 256 + threadIdx.x;
    if (i < n) {
        float v = src[i];
        __nv_bfloat16 h = __float2bfloat16(v);
        hi[i] = h;
        lo[i] = __float2bfloat16(v - __bfloat162float(h));
    }
}

// ---------------- W[K,N] -> Wt_hi/lo[N,K] transpose + split ------------------
__global__ __launch_bounds__(256) void tsplit(
    const float* __restrict__ W, __nv_bfloat16* __restrict__ hi,
    __nv_bfloat16* __restrict__ lo, int K, int N) {
    __shared__ float t[32][33];
    const int n0 = blockIdx.x * 32, k0 = blockIdx.y * 32;
    const int tx = threadIdx.x & 31, ty = threadIdx.x >> 5;   // 32 x 8
#pragma unroll
    for (int j = 0; j < 4; j++)
        t[ty + 8 * j][tx] = W[(size_t)(k0 + ty + 8 * j) * N + n0 + tx];
    __syncthreads();
#pragma unroll
    for (int j = 0; j < 4; j++) {
        float v = t[tx][ty + 8 * j];
        __nv_bfloat16 h = __float2bfloat16(v);
        size_t o = (size_t)(n0 + ty + 8 * j) * K + k0 + tx;
        hi[o] = h;
        lo[o] = __float2bfloat16(v - __bfloat162float(h));
    }
}

// ---------------- ba projection: 4 rows per warp -----------------------------
__global__ __launch_bounds__(256) void ba_kernel(
    const float* __restrict__ x, const float* __restrict__ Wba,
    const float* __restrict__ dt_bias, const float* __restrict__ A_log) {
    const int gw4 = (int)((blockIdx.x * 256 + threadIdx.x) >> 5);  // warp idx
    const int lane = threadIdx.x & 31;
    const int row0 = gw4 * 4;
    if (row0 >= MM) return;
    const float* xr0 = x + (size_t)row0 * 1024;

    float acc[4][16];
#pragma unroll
    for (int r = 0; r < 4; r++)
#pragma unroll
        for (int j = 0; j < 16; j++) acc[r][j] = 0.f;

    for (int i = lane; i < 1024; i += 32) {
        const float4* wr = (const float4*)(Wba + (size_t)i * 16);
        float4 w0 = wr[0], w1 = wr[1], w2 = wr[2], w3 = wr[3];
        float xv[4] = {xr0[i], xr0[1024 + i], xr0[2048 + i], xr0[3072 + i]};
#pragma unroll
        for (int r = 0; r < 4; r++) {
            acc[r][0] = fmaf(xv[r], w0.x, acc[r][0]);
            acc[r][1] = fmaf(xv[r], w0.y, acc[r][1]);
            acc[r][2] = fmaf(xv[r], w0.z, acc[r][2]);
            acc[r][3] = fmaf(xv[r], w0.w, acc[r][3]);
            acc[r][4] = fmaf(xv[r], w1.x, acc[r][4]);
            acc[r][5] = fmaf(xv[r], w1.y, acc[r][5]);
            acc[r][6] = fmaf(xv[r], w1.z, acc[r][6]);
            acc[r][7] = fmaf(xv[r], w1.w, acc[r][7]);
            acc[r][8] = fmaf(xv[r], w2.x, acc[r][8]);
            acc[r][9] = fmaf(xv[r], w2.y, acc[r][9]);
            acc[r][10] = fmaf(xv[r], w2.z, acc[r][10]);
            acc[r][11] = fmaf(xv[r], w2.w, acc[r][11]);
            acc[r][12] = fmaf(xv[r], w3.x, acc[r][12]);
            acc[r][13] = fmaf(xv[r], w3.y, acc[r][13]);
            acc[r][14] = fmaf(xv[r], w3.z, acc[r][14]);
            acc[r][15] = fmaf(xv[r], w3.w, acc[r][15]);
        }
    }
#pragma unroll
    for (int r = 0; r < 4; r++) {
#pragma unroll
        for (int j = 0; j < 16; j++) {
#pragma unroll
            for (int s = 16; s; s >>= 1)
                acc[r][j] += __shfl_xor_sync(0xffffffffu, acc[r][j], s);
        }
        if (lane < 8) {
            const int h = lane;
            const int gw = row0 + r;
            float bet = 1.0f / (1.0f + expf(-acc[r][h]));
            float al = acc[r][8 + h] + dt_bias[h];
            float sp = (al > 20.0f) ? al : log1pf(expf(al));
            float g = -expf(A_log[h]) * sp;
            const int b = gw >> 12, t = gw & (TT - 1);
            size_t o = ((size_t)(b * HH + h)) * TT + t;
            g_be[o] = bet;
            g_eg[o] = expf(g);
        }
    }
}

// ------- depthwise causal conv (K=4) + SiLU, 4 t per thread, scatter --------
__global__ __launch_bounds__(256) void conv_kernel(
    const float* __restrict__ cw, const float* __restrict__ cb) {
    const size_t idx = (size_t)blockIdx.x * 256 + threadIdx.x;
    const size_t total = (size_t)BB * (TT / 4) * 3072;
    if (idx >= total) return;
    const int c = (int)(idx % 3072);
    const size_t bt4 = idx / 3072;
    const int b = (int)(bt4 >> 10);            // TT/4 = 1024 per batch
    const int t0 = ((int)(bt4 & 1023)) << 2;

    const float* row = g_qkvz + ((size_t)b * TT + t0) * 4096 + c;
    float xv[7];
#pragma unroll
    for (int j = 0; j < 7; j++) {
        int tt = t0 - 3 + j;
        xv[j] = (tt >= 0) ? row[(size_t)(j - 3) * 4096] : 0.f;
    }
    const float* w = cw + (size_t)c * 4;
    const float w0 = w[0], w1 = w[1], w2 = w[2], w3 = w[3];
    const float bias = cb[c];

    const int h = (c >> 7) & 7;
    const int d = c & 127;
    const int sec = c >> 10;                   // 0=q 1=k 2=v
    float* outp;
    float scale;
    if (sec == 0)      { outp = g_q; scale = 0.08838834764831845f; }
    else if (sec == 1) { outp = g_k; scale = 1.f; }
    else               { outp = g_v; scale = 1.f; }
    const size_t obase = (((size_t)(b * HH + h)) * TT + t0) * DD + d;

#pragma unroll
    for (int i = 0; i < 4; i++) {
        float y = bias;
        y = fmaf(xv[i], w0, y);
        y = fmaf(xv[i + 1], w1, y);
        y = fmaf(xv[i + 2], w2, y);
        y = fmaf(xv[i + 3], w3, y);
        float o = y / (1.0f + expf(-y)) * scale;
        outp[obase + (size_t)i * DD] = o;
    }
}

// ---------------- gated delta rule: smem-staged sequential scan --------------
// 256 blocks (32 bh x 8 v-splits), 128 threads, 2 blocks/SM co-resident:
// two independent scans interleave on one SM, hiding each other's shfl-chain
// latency. Per-thread shape identical to the proven R11 kernel: 16 rows x 1
// col of S, 8 threads/col, 3-shfl reductions, deferred o-store.
#define SC_CHUNK 16
#define SC_NCHUNK (TT / SC_CHUNK)      // 256
#define SC_GSTRIDE 1040                // bytes between 16-row groups (8 groups)
#define SC_KBYTES (8 * SC_GSTRIDE)     // 8320
#define SC_VOFF  (2 * SC_KBYTES)       // 16640 (v: 16 t x 16 cols = 1024 B)
#define SC_EGOFF (SC_VOFF + 1024)      // 17664
#define SC_BEOFF (SC_EGOFF + 64)       // 17728
#define SC_BUFB  17792

__global__ __launch_bounds__(128, 2) void scan_kernel() {
    __shared__ __align__(16) char sscan[2][SC_BUFB];

    const int bh = blockIdx.x >> 3;
    const int split = blockIdx.x & 7;        // 8 splits of 16 cols
    const int tid = threadIdx.x;
    const int colloc = tid >> 3;             // 0..15 (local col)
    const int g = tid & 7;                   // row group, rows g*16..g*16+15
    const int b = bh >> 3, h = bh & 7;

    const float* kbase = g_k + (size_t)bh * TT * DD;
    const float* qbase = g_q + (size_t)bh * TT * DD;
    const float* vbase = g_v + (size_t)bh * TT * DD + split * 16;
    const float* egbase = g_eg + (size_t)bh * TT;
    const float* bebase = g_be + (size_t)bh * TT;
    float* ob = g_core + (size_t)b * TT * 1024 + (size_t)h * DD
              + (split << 4) + colloc;

    // loader roles per chunk: k/q 4 chunks each (512 16B-chunks per matrix)
    const uint32_t sb0 = smem_u32(&sscan[0][0]);
    const uint32_t sb1 = smem_u32(&sscan[1][0]);
    uint32_t kd[4];
    int ktA[4], kjA[4];
#pragma unroll
    for (int r = 0; r < 4; r++) {
        int ch = tid + r * 128;
        ktA[r] = ch >> 5; kjA[r] = ch & 31;
        kd[r] = (uint32_t)((kjA[r] >> 2) * SC_GSTRIDE + ktA[r] * 64 + (kjA[r] & 3) * 16);
    }

#define SC_LOAD(cc, buf) do { \
        const uint32_t bp = (buf) ? sb1 : sb0; \
        size_t t0_ = (size_t)(cc) * SC_CHUNK; \
        _Pragma("unroll") \
        for (int r_ = 0; r_ < 4; r_++) { \
            cp_async16(bp + kd[r_], kbase + (t0_ + ktA[r_]) * 128 + kjA[r_] * 4); \
            cp_async16(bp + SC_KBYTES + kd[r_], qbase + (t0_ + ktA[r_]) * 128 + kjA[r_] * 4); \
        } \
        if (tid < 64) { \
            int vt_ = tid >> 2, vj_ = tid & 3; \
            cp_async16(bp + SC_VOFF + vt_ * 64 + vj_ * 16, \
                       vbase + (t0_ + vt_) * 128 + vj_ * 4); \
        } else if (tid < 68) { \
            cp_async16(bp + SC_EGOFF + (tid - 64) * 16, egbase + t0_ + (tid - 64) * 4); \
        } else if (tid < 72) { \
            cp_async16(bp + SC_BEOFF + (tid - 68) * 16, bebase + t0_ + (tid - 68) * 4); \
        } \
        CP_COMMIT(); \
    } while (0)

    float S[16];
#pragma unroll
    for (int i = 0; i < 16; i++) S[i] = 0.f;
    float oprev = 0.f;
    const bool leader = (tid & 7) == 0;

    SC_LOAD(0, 0);
    SC_LOAD(1, 1);

    for (int c = 0; c < SC_NCHUNK; c++) {
        CP_WAIT1();                  // chunk c landed (own loads)
        __syncthreads();             // all threads' chunk-c loads visible

        const char* bufp = &sscan[c & 1][0];
        const float4* kg = (const float4*)(bufp + (size_t)g * SC_GSTRIDE);
        const float4* qg = (const float4*)(bufp + SC_KBYTES + (size_t)g * SC_GSTRIDE);
        const float* vsp = (const float*)(bufp + SC_VOFF) + colloc;
        const float* egp = (const float*)(bufp + SC_EGOFF);
        const float* bep = (const float*)(bufp + SC_BEOFF);

#pragma unroll 4
        for (int tt = 0; tt < SC_CHUNK; tt++) {
            float4 k0 = kg[tt * 4 + 0], k1 = kg[tt * 4 + 1],
                   k2 = kg[tt * 4 + 2], k3 = kg[tt * 4 + 3];
            float4 q0 = qg[tt * 4 + 0], q1 = qg[tt * 4 + 1],
                   q2 = qg[tt * 4 + 2], q3 = qg[tt * 4 + 3];
            const float vt = vsp[tt * 16];
            const float egt = egp[tt];
            const float bet = bep[tt];
            float kr[16], qr[16];
#pragma unroll
            for (int i = 0; i < 4; i++) {
                kr[i] = ((const float*)&k0)[i];  kr[4 + i] = ((const float*)&k1)[i];
                kr[8 + i] = ((const float*)&k2)[i]; kr[12 + i] = ((const float*)&k3)[i];
                qr[i] = ((const float*)&q0)[i];  qr[4 + i] = ((const float*)&q1)[i];
                qr[8 + i] = ((const float*)&q2)[i]; qr[12 + i] = ((const float*)&q3)[i];
            }

            // deferred reduce of previous step's output (independent chain)
            float ord = oprev;
            ord += __shfl_xor_sync(0xffffffffu, ord, 1);

            // s = k . S_old over this thread's 16 rows
            float s0 = 0.f, s1 = 0.f, s2 = 0.f, s3 = 0.f;
#pragma unroll
            for (int i = 0; i < 4; i++) {
                s0 = fmaf(kr[i],      S[i],      s0);
                s1 = fmaf(kr[4 + i],  S[4 + i],  s1);
                s2 = fmaf(kr[8 + i],  S[8 + i],  s2);
                s3 = fmaf(kr[12 + i], S[12 + i], s3);
            }
            ord += __shfl_xor_sync(0xffffffffu, ord, 2);
            float s = (s0 + s1) + (s2 + s3);
            ord += __shfl_xor_sync(0xffffffffu, ord, 4);
            s += __shfl_xor_sync(0xffffffffu, s, 1);
            const int t = c * SC_CHUNK + tt;
            if (leader && t) ob[(size_t)(t - 1) * 1024] = ord;
            s += __shfl_xor_sync(0xffffffffu, s, 2);
            s += __shfl_xor_sync(0xffffffffu, s, 4);
            const float delta = (vt - egt * s) * bet;

            // S = eg*S + k*delta ; o partial = q . S_new
            float o0 = 0.f, o1 = 0.f, o2 = 0.f, o3 = 0.f;
#pragma unroll
            for (int i = 0; i < 4; i++) {
                S[i]      = fmaf(kr[i],      delta, egt * S[i]);
                o0 = fmaf(qr[i], S[i], o0);
                S[4 + i]  = fmaf(kr[4 + i],  delta, egt * S[4 + i]);
                o1 = fmaf(qr[4 + i], S[4 + i], o1);
                S[8 + i]  = fmaf(kr[8 + i],  delta, egt * S[8 + i]);
                o2 = fmaf(qr[8 + i], S[8 + i], o2);
                S[12 + i] = fmaf(kr[12 + i], delta, egt * S[12 + i]);
                o3 = fmaf(qr[12 + i], S[12 + i], o3);
            }
            oprev = (o0 + o1) + (o2 + o3);
        }

        __syncthreads();             // all threads done reading buf (c&1)
        if (c + 2 < SC_NCHUNK) SC_LOAD(c + 2, c & 1);
        else CP_COMMIT();            // keep group accounting exact
    }

    // final deferred store (t = TT-1)
    float ord = oprev;
    ord += __shfl_xor_sync(0xffffffffu, ord, 1);
    ord += __shfl_xor_sync(0xffffffffu, ord, 2);
    ord += __shfl_xor_sync(0xffffffffu, ord, 4);
    if (leader) ob[(size_t)(TT - 1) * 1024] = ord;
#undef SC_LOAD
}

// ---------------- fused RMSNorm * w * silu(z) -> bf16 hi/lo ------------------
__global__ __launch_bounds__(256) void gate_kernel(const float* __restrict__ nw) {
    const int bt = blockIdx.x;
    const int tid = threadIdx.x;
    const float* cr = g_core + (size_t)bt * 1024;
    const float* zr = g_qkvz + (size_t)bt * 4096 + 3072;

    float cs[4];
    float ss = 0.f;
#pragma unroll
    for (int u = 0; u < 4; u++) {
        cs[u] = cr[tid + u * 256];
        ss = fmaf(cs[u], cs[u], ss);
    }
#pragma unroll
    for (int s = 16; s; s >>= 1) ss += __shfl_xor_sync(0xffffffffu, ss, s);
    __shared__ float ws[8];
    if ((tid & 31) == 0) ws[tid >> 5] = ss;
    __syncthreads();
    float tot = ws[0] + ws[1] + ws[2] + ws[3] + ws[4] + ws[5] + ws[6] + ws[7];
    const float rms = rsqrtf(tot * (1.0f / 1024.0f) + 1e-6f);

#pragma unroll
    for (int u = 0; u < 4; u++) {
        const int i = tid + u * 256;
        float z = zr[i];
        float sz = z / (1.0f + expf(-z));
        float fv = cs[u] * rms * nw[i] * sz;
        __nv_bfloat16 hbits = __float2bfloat16(fv);
        size_t o = (size_t)bt * 1024 + i;
        g_fhi[o] = hbits;
        g_flo[o] = __float2bfloat16(fv - __bfloat162float(hbits));
    }
}

// ---------------- launch ------------------------------------------------------
extern "C" void kernel_launch(void* const* d_in, const int* in_sizes, int n_in,
                              void* d_out, int out_size) {
    const float* x       = (const float*)d_in[0];
    const float* W_qkvz  = (const float*)d_in[1];
    const float* W_ba    = (const float*)d_in[2];
    const float* conv_w  = (const float*)d_in[3];
    const float* conv_b  = (const float*)d_in[4];
    const float* dt_bias = (const float*)d_in[5];
    const float* A_log   = (const float*)d_in[6];
    const float* norm_w  = (const float*)d_in[7];
    const float* W_out   = (const float*)d_in[8];
    float* out = (float*)d_out;

    // idempotent; not stream-ordered, capture-safe
    (void)cudaFuncSetAttribute(hmma_gemm,
        cudaFuncAttributeMaxDynamicSharedMemorySize, GEMM_SMEM);

    float* qkvz_ptr;  cudaGetSymbolAddress((void**)&qkvz_ptr, g_qkvz);
    __nv_bfloat16 *xhi, *xlo, *wqh, *wql, *woh, *wol, *fhi, *flo;
    cudaGetSymbolAddress((void**)&xhi, g_xhi);
    cudaGetSymbolAddress((void**)&xlo, g_xlo);
    cudaGetSymbolAddress((void**)&wqh, g_wqt_hi);
    cudaGetSymbolAddress((void**)&wql, g_wqt_lo);
    cudaGetSymbolAddress((void**)&woh, g_wot_hi);
    cudaGetSymbolAddress((void**)&wol, g_wot_lo);
    cudaGetSymbolAddress((void**)&fhi, g_fhi);
    cudaGetSymbolAddress((void**)&flo, g_flo);

    const int M = MM;  // 16384

    // 0) operand prep: split x; transpose+split weights
    split_f32<<<(M * KDIM) / 256, 256>>>(x, xhi, xlo, M * KDIM);
    tsplit<<<dim3(4096 / 32, KDIM / 32), 256>>>(W_qkvz, wqh, wql, KDIM, 4096);
    tsplit<<<dim3(1024 / 32, KDIM / 32), 256>>>(W_out, woh, wol, KDIM, 1024);

    // 1) qkvz = x @ W_qkvz  (HMMA split-bf16)
    hmma_gemm<<<dim3(4096 / 128, M / 128), 256, GEMM_SMEM>>>(
        xhi, xlo, wqh, wql, qkvz_ptr, 4096);

    // 2) ba projection + beta / exp(g)
    ba_kernel<<<(M / 4) * 32 / 256, 256>>>(x, W_ba, dt_bias, A_log);
    // 3) causal depthwise conv + SiLU -> q,k,v
    conv_kernel<<<(unsigned)(((size_t)BB * (TT / 4) * 3072 + 255) / 256), 256>>>(
        conv_w, conv_b);
    // 4) gated delta rule scan (smem-staged, 256 blocks x 128 thr, 2/SM)
    scan_kernel<<<256, 128>>>();
    // 5) RMSNorm-gate -> fused hi/lo
    gate_kernel<<<M, 256>>>(norm_w);
    // 6) out = fused @ W_out  (HMMA split-bf16)
    hmma_gemm<<<dim3(1024 / 128, M / 128), 256, GEMM_SMEM>>>(
        fhi, flo, woh, wol, out, 1024);
}

// round 16
// speedup vs baseline: 1.3310x; 1.0651x over previous
#include <cuda_runtime.h>
#include <cuda_bf16.h>
#include <math.h>
#include <stdint.h>

// Problem constants
#define BB 4
#define TT 4096
#define HH 8
#define DD 128
#define MM (BB*TT)     // 16384
#define KDIM 1024

// ---------------- scratch (device globals: no allocs allowed) ----------------
__device__ __align__(16) float g_qkvz[(size_t)MM * 4096];
__device__ __align__(16) float g_q[(size_t)BB * HH * TT * DD];
__device__ __align__(16) float g_k[(size_t)BB * HH * TT * DD];
__device__ __align__(16) float g_v[(size_t)BB * HH * TT * DD];
__device__ __align__(16) float g_eg[(size_t)BB * HH * TT];
__device__ __align__(16) float g_be[(size_t)BB * HH * TT];
__device__ __align__(16) float g_core[(size_t)BB * TT * 1024];
// split-bf16 operands
__device__ __align__(16) __nv_bfloat16 g_xhi[(size_t)MM * KDIM];
__device__ __align__(16) __nv_bfloat16 g_xlo[(size_t)MM * KDIM];
__device__ __align__(16) __nv_bfloat16 g_wqt_hi[(size_t)4096 * KDIM];  // W_qkvz^T [N,K]
__device__ __align__(16) __nv_bfloat16 g_wqt_lo[(size_t)4096 * KDIM];
__device__ __align__(16) __nv_bfloat16 g_wot_hi[(size_t)1024 * KDIM];  // W_out^T [N,K]
__device__ __align__(16) __nv_bfloat16 g_wot_lo[(size_t)1024 * KDIM];
__device__ __align__(16) __nv_bfloat16 g_fhi[(size_t)MM * KDIM];
__device__ __align__(16) __nv_bfloat16 g_flo[(size_t)MM * KDIM];

// ============================ helpers ========================================
__device__ __forceinline__ uint32_t smem_u32(const void* p) {
    return (uint32_t)__cvta_generic_to_shared(p);
}
__device__ __forceinline__ void cp_async16(uint32_t dst, const void* src) {
    asm volatile("cp.async.cg.shared.global [%0], [%1], 16;\n" :: "r"(dst), "l"(src));
}
#define CP_COMMIT() asm volatile("cp.async.commit_group;\n" ::: "memory")
#define CP_WAIT1()  asm volatile("cp.async.wait_group 1;\n" ::: "memory")

__device__ __forceinline__ void ldm4(uint32_t* r, uint32_t addr) {
    asm volatile("ldmatrix.sync.aligned.m8n8.x4.shared.b16 {%0,%1,%2,%3}, [%4];"
                 : "=r"(r[0]), "=r"(r[1]), "=r"(r[2]), "=r"(r[3]) : "r"(addr));
}
__device__ __forceinline__ void mma16816(float* c, const uint32_t* a,
                                         const uint32_t* b) {
    asm volatile(
        "mma.sync.aligned.m16n8k16.row.col.f32.bf16.bf16.f32 "
        "{%0,%1,%2,%3}, {%4,%5,%6,%7}, {%8,%9}, {%0,%1,%2,%3};"
        : "+f"(c[0]), "+f"(c[1]), "+f"(c[2]), "+f"(c[3])
        : "r"(a[0]), "r"(a[1]), "r"(a[2]), "r"(a[3]), "r"(b[0]), "r"(b[1]));
}

// ============ HMMA split-bf16 GEMM: C[M,N] = A[M,K] @ Bt[N,K]^T ==============
// BM=BN=128, BK=32, 256 threads (2x4 warps, 64x32 warp tiles).
// XOR-swizzled 64B rows, 3-stage cp.async pipeline, 2 CTAs/SM.
#define MATB  8192               // 128 rows * 64 B
#define STGB  (4 * MATB)         // 32768: Ahi,Alo,Bhi,Blo
#define NSTG  3
#define GEMM_SMEM (NSTG * STGB)  // 98304

__global__ __launch_bounds__(256, 2) void hmma_gemm(
    const __nv_bfloat16* __restrict__ Ahi, const __nv_bfloat16* __restrict__ Alo,
    const __nv_bfloat16* __restrict__ Bhi, const __nv_bfloat16* __restrict__ Blo,
    float* __restrict__ C, int ldc) {
    extern __shared__ __align__(128) char smem[];
    const int tid = threadIdx.x;
    const int wid = tid >> 5, lane = tid & 31;
    const int wm = wid >> 2, wn = wid & 3;          // warp grid 2 x 4
    const int n0 = blockIdx.x << 7;
    const int m0 = blockIdx.y << 7;
    const uint32_t sb = smem_u32(smem);

    const int row_ld = tid >> 1;
    const int c0 = (tid & 1) * 2;
    const uint32_t selL = ((uint32_t)row_ld >> 1) & 3;
    const uint32_t soR = (uint32_t)row_ld * 64;
    const uint32_t sc0 = soR + (((uint32_t)c0 ^ selL) * 16);
    const uint32_t sc1 = soR + ((((uint32_t)c0 + 1) ^ selL) * 16);
    const __nv_bfloat16* pAhi = Ahi + (size_t)(m0 + row_ld) * KDIM;
    const __nv_bfloat16* pAlo = Alo + (size_t)(m0 + row_ld) * KDIM;
    const __nv_bfloat16* pBhi = Bhi + (size_t)(n0 + row_ld) * KDIM;
    const __nv_bfloat16* pBlo = Blo + (size_t)(n0 + row_ld) * KDIM;

#define LOADST(s, kb) do { \
        uint32_t b_ = sb + (uint32_t)(s) * STGB; \
        size_t g0_ = (size_t)(kb) * 32 + c0 * 8; \
        cp_async16(b_ + 0 * MATB + sc0, pAhi + g0_); \
        cp_async16(b_ + 0 * MATB + sc1, pAhi + g0_ + 8); \
        cp_async16(b_ + 1 * MATB + sc0, pAlo + g0_); \
        cp_async16(b_ + 1 * MATB + sc1, pAlo + g0_ + 8); \
        cp_async16(b_ + 2 * MATB + sc0, pBhi + g0_); \
        cp_async16(b_ + 2 * MATB + sc1, pBhi + g0_ + 8); \
        cp_async16(b_ + 3 * MATB + sc0, pBlo + g0_); \
        cp_async16(b_ + 3 * MATB + sc1, pBlo + g0_ + 8); \
    } while (0)

    const uint32_t aBase = (uint32_t)(wm * 64 + (lane & 15)) * 64;
    const uint32_t selA = (((uint32_t)(lane & 15)) >> 1) & 3;
    const uint32_t abit = (uint32_t)(lane >> 4);
    const uint32_t aC0 = ((0 + abit) ^ selA) * 16;   // k16=0
    const uint32_t aC1 = ((2 + abit) ^ selA) * 16;   // k16=1
    const uint32_t bRow = ((uint32_t)(lane >> 4) << 3) + (uint32_t)(lane & 7);
    const uint32_t bBase = (uint32_t)(wn * 32 + (int)bRow) * 64;
    const uint32_t selB = (bRow >> 1) & 3;
    const uint32_t bbit = ((uint32_t)lane >> 3) & 1;
    const uint32_t bC0 = ((0 + bbit) ^ selB) * 16;
    const uint32_t bC1 = ((2 + bbit) ^ selB) * 16;

    float acc[4][4][4];
#pragma unroll
    for (int i = 0; i < 4; i++)
#pragma unroll
        for (int j = 0; j < 4; j++)
#pragma unroll
            for (int r = 0; r < 4; r++) acc[i][j][r] = 0.f;

    const int ITERS = KDIM / 32;   // 32
    LOADST(0, 0); CP_COMMIT();
    LOADST(1, 1); CP_COMMIT();

    int stage = 0;
    for (int it = 0; it < ITERS; it++) {
        CP_WAIT1();
        __syncthreads();
        if (it + 2 < ITERS) {
            int ns = stage + 2; if (ns >= 3) ns -= 3;
            LOADST(ns, it + 2);
        }
        CP_COMMIT();

        const uint32_t base = sb + (uint32_t)stage * STGB;
#pragma unroll
        for (int k16 = 0; k16 < 2; k16++) {
            const uint32_t aC = k16 ? aC1 : aC0;
            const uint32_t bC = k16 ? bC1 : bC0;
            uint32_t ah[4][4], bh[2][4], bl[2][4];
#pragma unroll
            for (int mf = 0; mf < 4; mf++)
                ldm4(ah[mf], base + 0 * MATB + aBase + mf * 1024 + aC);
#pragma unroll
            for (int p = 0; p < 2; p++) {
                ldm4(bh[p], base + 2 * MATB + bBase + p * 1024 + bC);
                ldm4(bl[p], base + 3 * MATB + bBase + p * 1024 + bC);
            }
#pragma unroll
            for (int mf = 0; mf < 4; mf++)
#pragma unroll
                for (int nf = 0; nf < 4; nf++)
                    mma16816(acc[mf][nf], ah[mf], &bh[nf >> 1][(nf & 1) * 2]);
#pragma unroll
            for (int mf = 0; mf < 4; mf++)
#pragma unroll
                for (int nf = 0; nf < 4; nf++)
                    mma16816(acc[mf][nf], ah[mf], &bl[nf >> 1][(nf & 1) * 2]);
            uint32_t al[4][4];
#pragma unroll
            for (int mf = 0; mf < 4; mf++)
                ldm4(al[mf], base + 1 * MATB + aBase + mf * 1024 + aC);
#pragma unroll
            for (int mf = 0; mf < 4; mf++)
#pragma unroll
                for (int nf = 0; nf < 4; nf++)
                    mma16816(acc[mf][nf], al[mf], &bh[nf >> 1][(nf & 1) * 2]);
        }
        if (++stage == 3) stage = 0;
    }

    // ---- epilogue ----
#pragma unroll
    for (int mf = 0; mf < 4; mf++) {
        const int r0 = m0 + wm * 64 + mf * 16 + (lane >> 2);
#pragma unroll
        for (int nf = 0; nf < 4; nf++) {
            const int c0e = n0 + wn * 32 + nf * 8 + (lane & 3) * 2;
            float2 v01 = make_float2(acc[mf][nf][0], acc[mf][nf][1]);
            float2 v23 = make_float2(acc[mf][nf][2], acc[mf][nf][3]);
            *(float2*)(C + (size_t)r0 * ldc + c0e) = v01;
            *(float2*)(C + (size_t)(r0 + 8) * ldc + c0e) = v23;
        }
    }
#undef LOADST
}

// ---------------- fp32 -> bf16 hi/lo split (elementwise) ---------------------
__global__ __launch_bounds__(256) void split_f32(
    const float* __restrict__ src, __nv_bfloat16* __restrict__ hi,
    __nv_bfloat16* __restrict__ lo, int n) {
    int i = blockIdx.x * 256 + threadIdx.x;
    if (i < n) {
        float v = src[i];
        __nv_bfloat16 h = __float2bfloat16(v);
        hi[i] = h;
        lo[i] = __float2bfloat16(v - __bfloat162float(h));
    }
}

// ---------------- W[K,N] -> Wt_hi/lo[N,K] transpose + split ------------------
__global__ __launch_bounds__(256) void tsplit(
    const float* __restrict__ W, __nv_bfloat16* __restrict__ hi,
    __nv_bfloat16* __restrict__ lo, int K, int N) {
    __shared__ float t[32][33];
    const int n0 = blockIdx.x * 32, k0 = blockIdx.y * 32;
    const int tx = threadIdx.x & 31, ty = threadIdx.x >> 5;   // 32 x 8
#pragma unroll
    for (int j = 0; j < 4; j++)
        t[ty + 8 * j][tx] = W[(size_t)(k0 + ty + 8 * j) * N + n0 + tx];
    __syncthreads();
#pragma unroll
    for (int j = 0; j < 4; j++) {
        float v = t[tx][ty + 8 * j];
        __nv_bfloat16 h = __float2bfloat16(v);
        size_t o = (size_t)(n0 + ty + 8 * j) * K + k0 + tx;
        hi[o] = h;
        lo[o] = __float2bfloat16(v - __bfloat162float(h));
    }
}

// ---------------- ba projection: 4 rows per warp -----------------------------
__global__ __launch_bounds__(256) void ba_kernel(
    const float* __restrict__ x, const float* __restrict__ Wba,
    const float* __restrict__ dt_bias, const float* __restrict__ A_log) {
    const int gw4 = (int)((blockIdx.x * 256 + threadIdx.x) >> 5);  // warp idx
    const int lane = threadIdx.x & 31;
    const int row0 = gw4 * 4;
    if (row0 >= MM) return;
    const float* xr0 = x + (size_t)row0 * 1024;

    float acc[4][16];
#pragma unroll
    for (int r = 0; r < 4; r++)
#pragma unroll
        for (int j = 0; j < 16; j++) acc[r][j] = 0.f;

    for (int i = lane; i < 1024; i += 32) {
        const float4* wr = (const float4*)(Wba + (size_t)i * 16);
        float4 w0 = wr[0], w1 = wr[1], w2 = wr[2], w3 = wr[3];
        float xv[4] = {xr0[i], xr0[1024 + i], xr0[2048 + i], xr0[3072 + i]};
#pragma unroll
        for (int r = 0; r < 4; r++) {
            acc[r][0] = fmaf(xv[r], w0.x, acc[r][0]);
            acc[r][1] = fmaf(xv[r], w0.y, acc[r][1]);
            acc[r][2] = fmaf(xv[r], w0.z, acc[r][2]);
            acc[r][3] = fmaf(xv[r], w0.w, acc[r][3]);
            acc[r][4] = fmaf(xv[r], w1.x, acc[r][4]);
            acc[r][5] = fmaf(xv[r], w1.y, acc[r][5]);
            acc[r][6] = fmaf(xv[r], w1.z, acc[r][6]);
            acc[r][7] = fmaf(xv[r], w1.w, acc[r][7]);
            acc[r][8] = fmaf(xv[r], w2.x, acc[r][8]);
            acc[r][9] = fmaf(xv[r], w2.y, acc[r][9]);
            acc[r][10] = fmaf(xv[r], w2.z, acc[r][10]);
            acc[r][11] = fmaf(xv[r], w2.w, acc[r][11]);
            acc[r][12] = fmaf(xv[r], w3.x, acc[r][12]);
            acc[r][13] = fmaf(xv[r], w3.y, acc[r][13]);
            acc[r][14] = fmaf(xv[r], w3.z, acc[r][14]);
            acc[r][15] = fmaf(xv[r], w3.w, acc[r][15]);
        }
    }
#pragma unroll
    for (int r = 0; r < 4; r++) {
#pragma unroll
        for (int j = 0; j < 16; j++) {
#pragma unroll
            for (int s = 16; s; s >>= 1)
                acc[r][j] += __shfl_xor_sync(0xffffffffu, acc[r][j], s);
        }
        if (lane < 8) {
            const int h = lane;
            const int gw = row0 + r;
            float bet = 1.0f / (1.0f + expf(-acc[r][h]));
            float al = acc[r][8 + h] + dt_bias[h];
            float sp = (al > 20.0f) ? al : log1pf(expf(al));
            float g = -expf(A_log[h]) * sp;
            const int b = gw >> 12, t = gw & (TT - 1);
            size_t o = ((size_t)(b * HH + h)) * TT + t;
            g_be[o] = bet;
            g_eg[o] = expf(g);
        }
    }
}

// ------- depthwise causal conv (K=4) + SiLU, 4 t per thread, scatter --------
__global__ __launch_bounds__(256) void conv_kernel(
    const float* __restrict__ cw, const float* __restrict__ cb) {
    const size_t idx = (size_t)blockIdx.x * 256 + threadIdx.x;
    const size_t total = (size_t)BB * (TT / 4) * 3072;
    if (idx >= total) return;
    const int c = (int)(idx % 3072);
    const size_t bt4 = idx / 3072;
    const int b = (int)(bt4 >> 10);            // TT/4 = 1024 per batch
    const int t0 = ((int)(bt4 & 1023)) << 2;

    const float* row = g_qkvz + ((size_t)b * TT + t0) * 4096 + c;
    float xv[7];
#pragma unroll
    for (int j = 0; j < 7; j++) {
        int tt = t0 - 3 + j;
        xv[j] = (tt >= 0) ? row[(size_t)(j - 3) * 4096] : 0.f;
    }
    const float* w = cw + (size_t)c * 4;
    const float w0 = w[0], w1 = w[1], w2 = w[2], w3 = w[3];
    const float bias = cb[c];

    const int h = (c >> 7) & 7;
    const int d = c & 127;
    const int sec = c >> 10;                   // 0=q 1=k 2=v
    float* outp;
    float scale;
    if (sec == 0)      { outp = g_q; scale = 0.08838834764831845f; }
    else if (sec == 1) { outp = g_k; scale = 1.f; }
    else               { outp = g_v; scale = 1.f; }
    const size_t obase = (((size_t)(b * HH + h)) * TT + t0) * DD + d;

#pragma unroll
    for (int i = 0; i < 4; i++) {
        float y = bias;
        y = fmaf(xv[i], w0, y);
        y = fmaf(xv[i + 1], w1, y);
        y = fmaf(xv[i + 2], w2, y);
        y = fmaf(xv[i + 3], w3, y);
        float o = y / (1.0f + expf(-y)) * scale;
        outp[obase + (size_t)i * DD] = o;
    }
}

// ---------------- gated delta rule: smem-staged sequential scan --------------
// 128 blocks (32 bh x 4 v-splits of 32 cols), 128 threads. Thread owns
// 16 rows x 2 COLUMNS: same kr/qr registers serve two independent delta-rule
// columns -> k/q smem traffic halves vs R11 (crossbar was co-binding) while
// per-SM FMA work is unchanged. Per-column FMA/reduce order identical to R11.
#define SC_CHUNK 16
#define SC_NCHUNK (TT / SC_CHUNK)      // 256
#define SC_GSTRIDE 1040                // bytes between 16-row groups (8 groups)
#define SC_KBYTES (8 * SC_GSTRIDE)     // 8320
#define SC_VOFF  (2 * SC_KBYTES)       // 16640 (v: 16 t x 32 cols = 2048 B)
#define SC_EGOFF (SC_VOFF + 2048)      // 18688
#define SC_BEOFF (SC_EGOFF + 64)       // 18752
#define SC_BUFB  18816

__global__ __launch_bounds__(128, 1) void scan_kernel() {
    __shared__ __align__(16) char sscan[2][SC_BUFB];

    const int bh = blockIdx.x >> 2;
    const int split = blockIdx.x & 3;        // 4 splits of 32 cols
    const int tid = threadIdx.x;
    const int cp = tid >> 3;                 // 0..15 column-pair
    const int g = tid & 7;                   // row group, rows g*16..g*16+15
    const int b = bh >> 3, h = bh & 7;

    const float* kbase = g_k + (size_t)bh * TT * DD;
    const float* qbase = g_q + (size_t)bh * TT * DD;
    const float* vbase = g_v + (size_t)bh * TT * DD + split * 32;
    const float* egbase = g_eg + (size_t)bh * TT;
    const float* bebase = g_be + (size_t)bh * TT;
    float* ob0 = g_core + (size_t)b * TT * 1024 + (size_t)h * DD
               + (split << 5) + 2 * cp;
    float* ob1 = ob0 + 1;

    // loader roles per chunk: k/q 4 chunks each (512 16B-chunks per matrix)
    const uint32_t sb0 = smem_u32(&sscan[0][0]);
    const uint32_t sb1 = smem_u32(&sscan[1][0]);
    uint32_t kd[4];
    int ktA[4], kjA[4];
#pragma unroll
    for (int r = 0; r < 4; r++) {
        int ch = tid + r * 128;
        ktA[r] = ch >> 5; kjA[r] = ch & 31;
        kd[r] = (uint32_t)((kjA[r] >> 2) * SC_GSTRIDE + ktA[r] * 64 + (kjA[r] & 3) * 16);
    }
    const int vt_ = tid >> 3, vj_ = tid & 7;   // v: 128 chunks (16 t x 8)

#define SC_LOAD(cc, buf) do { \
        const uint32_t bp = (buf) ? sb1 : sb0; \
        size_t t0_ = (size_t)(cc) * SC_CHUNK; \
        _Pragma("unroll") \
        for (int r_ = 0; r_ < 4; r_++) { \
            cp_async16(bp + kd[r_], kbase + (t0_ + ktA[r_]) * 128 + kjA[r_] * 4); \
            cp_async16(bp + SC_KBYTES + kd[r_], qbase + (t0_ + ktA[r_]) * 128 + kjA[r_] * 4); \
        } \
        cp_async16(bp + SC_VOFF + vt_ * 128 + vj_ * 16, \
                   vbase + (t0_ + vt_) * 128 + vj_ * 4); \
        if (tid < 4) { \
            cp_async16(bp + SC_EGOFF + tid * 16, egbase + t0_ + tid * 4); \
        } else if (tid < 8) { \
            cp_async16(bp + SC_BEOFF + (tid - 4) * 16, bebase + t0_ + (tid - 4) * 4); \
        } \
        CP_COMMIT(); \
    } while (0)

    float Sa[16], Sb[16];
#pragma unroll
    for (int i = 0; i < 16; i++) { Sa[i] = 0.f; Sb[i] = 0.f; }
    float oprev_a = 0.f, oprev_b = 0.f;
    const bool leader = (tid & 7) == 0;

    SC_LOAD(0, 0);
    SC_LOAD(1, 1);

    for (int c = 0; c < SC_NCHUNK; c++) {
        CP_WAIT1();                  // chunk c landed (own loads)
        __syncthreads();             // all threads' chunk-c loads visible

        const char* bufp = &sscan[c & 1][0];
        const float4* kg = (const float4*)(bufp + (size_t)g * SC_GSTRIDE);
        const float4* qg = (const float4*)(bufp + SC_KBYTES + (size_t)g * SC_GSTRIDE);
        const float* vsp = (const float*)(bufp + SC_VOFF);
        const float* egp = (const float*)(bufp + SC_EGOFF);
        const float* bep = (const float*)(bufp + SC_BEOFF);

#pragma unroll 4
        for (int tt = 0; tt < SC_CHUNK; tt++) {
            float4 k0 = kg[tt * 4 + 0], k1 = kg[tt * 4 + 1],
                   k2 = kg[tt * 4 + 2], k3 = kg[tt * 4 + 3];
            float4 q0 = qg[tt * 4 + 0], q1 = qg[tt * 4 + 1],
                   q2 = qg[tt * 4 + 2], q3 = qg[tt * 4 + 3];
            const float* vrow = vsp + tt * 32;
            const float vta = vrow[2 * cp];
            const float vtb = vrow[2 * cp + 1];
            const float egt = egp[tt];
            const float bet = bep[tt];
            float kr[16], qr[16];
#pragma unroll
            for (int i = 0; i < 4; i++) {
                kr[i] = ((const float*)&k0)[i];  kr[4 + i] = ((const float*)&k1)[i];
                kr[8 + i] = ((const float*)&k2)[i]; kr[12 + i] = ((const float*)&k3)[i];
                qr[i] = ((const float*)&q0)[i];  qr[4 + i] = ((const float*)&q1)[i];
                qr[8 + i] = ((const float*)&q2)[i]; qr[12 + i] = ((const float*)&q3)[i];
            }

            // deferred reduce of previous step's outputs (independent chains)
            float orda = oprev_a, ordb = oprev_b;
            orda += __shfl_xor_sync(0xffffffffu, orda, 1);
            ordb += __shfl_xor_sync(0xffffffffu, ordb, 1);

            // s = k . S_old for both columns
            float a0 = 0.f, a1 = 0.f, a2 = 0.f, a3 = 0.f;
            float b0 = 0.f, b1 = 0.f, b2 = 0.f, b3 = 0.f;
#pragma unroll
            for (int i = 0; i < 4; i++) {
                a0 = fmaf(kr[i],      Sa[i],      a0);
                a1 = fmaf(kr[4 + i],  Sa[4 + i],  a1);
                a2 = fmaf(kr[8 + i],  Sa[8 + i],  a2);
                a3 = fmaf(kr[12 + i], Sa[12 + i], a3);
                b0 = fmaf(kr[i],      Sb[i],      b0);
                b1 = fmaf(kr[4 + i],  Sb[4 + i],  b1);
                b2 = fmaf(kr[8 + i],  Sb[8 + i],  b2);
                b3 = fmaf(kr[12 + i], Sb[12 + i], b3);
            }
            orda += __shfl_xor_sync(0xffffffffu, orda, 2);
            ordb += __shfl_xor_sync(0xffffffffu, ordb, 2);
            float sa = (a0 + a1) + (a2 + a3);
            float sb = (b0 + b1) + (b2 + b3);
            orda += __shfl_xor_sync(0xffffffffu, orda, 4);
            ordb += __shfl_xor_sync(0xffffffffu, ordb, 4);
            sa += __shfl_xor_sync(0xffffffffu, sa, 1);
            sb += __shfl_xor_sync(0xffffffffu, sb, 1);
            const int t = c * SC_CHUNK + tt;
            if (leader && t) {
                ob0[(size_t)(t - 1) * 1024] = orda;
                ob1[(size_t)(t - 1) * 1024] = ordb;
            }
            sa += __shfl_xor_sync(0xffffffffu, sa, 2);
            sb += __shfl_xor_sync(0xffffffffu, sb, 2);
            sa += __shfl_xor_sync(0xffffffffu, sa, 4);
            sb += __shfl_xor_sync(0xffffffffu, sb, 4);
            const float da = (vta - egt * sa) * bet;
            const float db = (vtb - egt * sb) * bet;

            // S = eg*S + k*delta ; o partial = q . S_new  (both columns)
            float oa0 = 0.f, oa1 = 0.f, oa2 = 0.f, oa3 = 0.f;
            float obp0 = 0.f, obp1 = 0.f, obp2 = 0.f, obp3 = 0.f;
#pragma unroll
            for (int i = 0; i < 4; i++) {
                Sa[i]      = fmaf(kr[i],      da, egt * Sa[i]);
                oa0 = fmaf(qr[i], Sa[i], oa0);
                Sa[4 + i]  = fmaf(kr[4 + i],  da, egt * Sa[4 + i]);
                oa1 = fmaf(qr[4 + i], Sa[4 + i], oa1);
                Sa[8 + i]  = fmaf(kr[8 + i],  da, egt * Sa[8 + i]);
                oa2 = fmaf(qr[8 + i], Sa[8 + i], oa2);
                Sa[12 + i] = fmaf(kr[12 + i], da, egt * Sa[12 + i]);
                oa3 = fmaf(qr[12 + i], Sa[12 + i], oa3);
                Sb[i]      = fmaf(kr[i],      db, egt * Sb[i]);
                obp0 = fmaf(qr[i], Sb[i], obp0);
                Sb[4 + i]  = fmaf(kr[4 + i],  db, egt * Sb[4 + i]);
                obp1 = fmaf(qr[4 + i], Sb[4 + i], obp1);
                Sb[8 + i]  = fmaf(kr[8 + i],  db, egt * Sb[8 + i]);
                obp2 = fmaf(qr[8 + i], Sb[8 + i], obp2);
                Sb[12 + i] = fmaf(kr[12 + i], db, egt * Sb[12 + i]);
                obp3 = fmaf(qr[12 + i], Sb[12 + i], obp3);
            }
            oprev_a = (oa0 + oa1) + (oa2 + oa3);
            oprev_b = (obp0 + obp1) + (obp2 + obp3);
        }

        __syncthreads();             // all threads done reading buf (c&1)
        if (c + 2 < SC_NCHUNK) SC_LOAD(c + 2, c & 1);
        else CP_COMMIT();            // keep group accounting exact
    }

    // final deferred stores (t = TT-1)
    float orda = oprev_a, ordb = oprev_b;
    orda += __shfl_xor_sync(0xffffffffu, orda, 1);
    ordb += __shfl_xor_sync(0xffffffffu, ordb, 1);
    orda += __shfl_xor_sync(0xffffffffu, orda, 2);
    ordb += __shfl_xor_sync(0xffffffffu, ordb, 2);
    orda += __shfl_xor_sync(0xffffffffu, orda, 4);
    ordb += __shfl_xor_sync(0xffffffffu, ordb, 4);
    if (leader) {
        ob0[(size_t)(TT - 1) * 1024] = orda;
        ob1[(size_t)(TT - 1) * 1024] = ordb;
    }
#undef SC_LOAD
}

// ---------------- fused RMSNorm * w * silu(z) -> bf16 hi/lo ------------------
__global__ __launch_bounds__(256) void gate_kernel(const float* __restrict__ nw) {
    const int bt = blockIdx.x;
    const int tid = threadIdx.x;
    const float* cr = g_core + (size_t)bt * 1024;
    const float* zr = g_qkvz + (size_t)bt * 4096 + 3072;

    float cs[4];
    float ss = 0.f;
#pragma unroll
    for (int u = 0; u < 4; u++) {
        cs[u] = cr[tid + u * 256];
        ss = fmaf(cs[u], cs[u], ss);
    }
#pragma unroll
    for (int s = 16; s; s >>= 1) ss += __shfl_xor_sync(0xffffffffu, ss, s);
    __shared__ float ws[8];
    if ((tid & 31) == 0) ws[tid >> 5] = ss;
    __syncthreads();
    float tot = ws[0] + ws[1] + ws[2] + ws[3] + ws[4] + ws[5] + ws[6] + ws[7];
    const float rms = rsqrtf(tot * (1.0f / 1024.0f) + 1e-6f);

#pragma unroll
    for (int u = 0; u < 4; u++) {
        const int i = tid + u * 256;
        float z = zr[i];
        float sz = z / (1.0f + expf(-z));
        float fv = cs[u] * rms * nw[i] * sz;
        __nv_bfloat16 hbits = __float2bfloat16(fv);
        size_t o = (size_t)bt * 1024 + i;
        g_fhi[o] = hbits;
        g_flo[o] = __float2bfloat16(fv - __bfloat162float(hbits));
    }
}

// ---------------- launch ------------------------------------------------------
extern "C" void kernel_launch(void* const* d_in, const int* in_sizes, int n_in,
                              void* d_out, int out_size) {
    const float* x       = (const float*)d_in[0];
    const float* W_qkvz  = (const float*)d_in[1];
    const float* W_ba    = (const float*)d_in[2];
    const float* conv_w  = (const float*)d_in[3];
    const float* conv_b  = (const float*)d_in[4];
    const float* dt_bias = (const float*)d_in[5];
    const float* A_log   = (const float*)d_in[6];
    const float* norm_w  = (const float*)d_in[7];
    const float* W_out   = (const float*)d_in[8];
    float* out = (float*)d_out;

    // idempotent; not stream-ordered, capture-safe
    (void)cudaFuncSetAttribute(hmma_gemm,
        cudaFuncAttributeMaxDynamicSharedMemorySize, GEMM_SMEM);

    float* qkvz_ptr;  cudaGetSymbolAddress((void**)&qkvz_ptr, g_qkvz);
    __nv_bfloat16 *xhi, *xlo, *wqh, *wql, *woh, *wol, *fhi, *flo;
    cudaGetSymbolAddress((void**)&xhi, g_xhi);
    cudaGetSymbolAddress((void**)&xlo, g_xlo);
    cudaGetSymbolAddress((void**)&wqh, g_wqt_hi);
    cudaGetSymbolAddress((void**)&wql, g_wqt_lo);
    cudaGetSymbolAddress((void**)&woh, g_wot_hi);
    cudaGetSymbolAddress((void**)&wol, g_wot_lo);
    cudaGetSymbolAddress((void**)&fhi, g_fhi);
    cudaGetSymbolAddress((void**)&flo, g_flo);

    const int M = MM;  // 16384

    // 0) operand prep: split x; transpose+split weights
    split_f32<<<(M * KDIM) / 256, 256>>>(x, xhi, xlo, M * KDIM);
    tsplit<<<dim3(4096 / 32, KDIM / 32), 256>>>(W_qkvz, wqh, wql, KDIM, 4096);
    tsplit<<<dim3(1024 / 32, KDIM / 32), 256>>>(W_out, woh, wol, KDIM, 1024);

    // 1) qkvz = x @ W_qkvz  (HMMA split-bf16)
    hmma_gemm<<<dim3(4096 / 128, M / 128), 256, GEMM_SMEM>>>(
        xhi, xlo, wqh, wql, qkvz_ptr, 4096);

    // 2) ba projection + beta / exp(g)
    ba_kernel<<<(M / 4) * 32 / 256, 256>>>(x, W_ba, dt_bias, A_log);
    // 3) causal depthwise conv + SiLU -> q,k,v
    conv_kernel<<<(unsigned)(((size_t)BB * (TT / 4) * 3072 + 255) / 256), 256>>>(
        conv_w, conv_b);
    // 4) gated delta rule scan (smem-staged, 2 cols/thread)
    scan_kernel<<<128, 128>>>();
    // 5) RMSNorm-gate -> fused hi/lo
    gate_kernel<<<M, 256>>>(norm_w);
    // 6) out = fused @ W_out  (HMMA split-bf16)
    hmma_gemm<<<dim3(1024 / 128, M / 128), 256, GEMM_SMEM>>>(
        fhi, flo, woh, wol, out, 1024);
}